// round 8
// baseline (speedup 1.0000x reference)
#include <cuda_runtime.h>
#include <cuda_bf16.h>

// RHS of 2-field Burgers-like PDE on nonuniform 2048x4096 grid.
// Inputs (metadata order): t[1], state[2*NX*NY], x[NX], y[NY], mu[1]
// Output: [2, NX, NY] float32.

#define NX_MAX 2048
#define NY_MAX 4096
#define FULLMASK 0xffffffffu
#define RT 4                      // i-rows per thread

// x-direction coefficients: AoS (warp-uniform broadcast loads)
__device__ float4 g_cxA[NX_MAX];   // (d1a, d1b, d1c, d2a)
__device__ float2 g_cxB[NX_MAX];   // (d2b, d2c)
// y-direction coefficients: SoA, 16B-aligned for float4 loads
__device__ __align__(16) float g_cy1a[NY_MAX];
__device__ __align__(16) float g_cy1b[NY_MAX];
__device__ __align__(16) float g_cy1c[NY_MAX];
__device__ __align__(16) float g_cy2a[NY_MAX];
__device__ __align__(16) float g_cy2b[NY_MAX];
__device__ __align__(16) float g_cy2c[NY_MAX];

__device__ __forceinline__ void stencil_coeffs(const float* __restrict__ g,
                                               int n, int k, float* c) {
    if (k == 0) {
        float hA = g[1] - g[0], hB = g[2] - g[1];
        c[0] = -(2.f * hA + hB) / (hA * (hA + hB));
        c[1] = (hA + hB) / (hA * hB);
        c[2] = -hA / (hB * (hA + hB));
        c[3] = 2.f / (hA * (hA + hB));
        c[4] = -2.f / (hA * hB);
        c[5] = 2.f / (hB * (hA + hB));
    } else if (k == n - 1) {
        float hC = g[n - 2] - g[n - 3], hD = g[n - 1] - g[n - 2];
        c[0] = hD / (hC * (hC + hD));
        c[1] = -(hC + hD) / (hC * hD);
        c[2] = (hC + 2.f * hD) / (hD * (hC + hD));
        c[3] = 2.f / (hC * (hC + hD));
        c[4] = -2.f / (hC * hD);
        c[5] = 2.f / (hD * (hC + hD));
    } else {
        float h1 = g[k] - g[k - 1], h2 = g[k + 1] - g[k];
        c[0] = -h2 / (h1 * (h1 + h2));
        c[1] = (h2 - h1) / (h1 * h2);
        c[2] = h1 / (h2 * (h1 + h2));
        c[3] = 2.f / (h1 * (h1 + h2));
        c[4] = -2.f / (h1 * h2);
        c[5] = 2.f / (h2 * (h1 + h2));
    }
}

__global__ __launch_bounds__(256)
void coeff_kernel(const float* __restrict__ x, int nx,
                  const float* __restrict__ y, int ny) {
    int k = blockIdx.x * blockDim.x + threadIdx.x;
    float c[6];
    if (k < nx) {
        stencil_coeffs(x, nx, k, c);
        g_cxA[k] = make_float4(c[0], c[1], c[2], c[3]);
        g_cxB[k] = make_float2(c[4], c[5]);
    }
    if (k < ny) {
        stencil_coeffs(y, ny, k, c);
        g_cy1a[k] = c[0]; g_cy1b[k] = c[1]; g_cy1c[k] = c[2];
        g_cy2a[k] = c[3]; g_cy2b[k] = c[4]; g_cy2c[k] = c[5];
    }
}

__device__ __forceinline__ float4 ld4(const float* p) {
    return *reinterpret_cast<const float4*>(p);
}
__device__ __forceinline__ void st4(float* p, float4 v) {
    *reinterpret_cast<float4*>(p) = v;
}

// Warp owns 128 aligned columns; lane owns 4 (float4). Rolling 4-row window
// (rows i-2..i+1): interior x-stencil = rows i-1,i,i+1; i==nx-1 one-sided =
// rows nx-3,nx-2,nx-1 (in window); i==0 row is fully zeroed by the reference
// so no x-stencil is needed there.
__global__ __launch_bounds__(128, 5)
void rhs_kernel(const float* __restrict__ state,
                const float* __restrict__ mu_p,
                float* __restrict__ out, int nx, int ny) {
    const int lane = threadIdx.x;
    const int base = blockIdx.x * 128;
    const int j0 = base + lane * 4;
    if (j0 >= ny) return;
    const int i0 = (blockIdx.y * blockDim.y + threadIdx.y) * RT;
    const unsigned plane = (unsigned)nx * (unsigned)ny;
    const float* __restrict__ u = state;
    const float* __restrict__ v = state + plane;
    const float mu = mu_p[0];

    // y-coefficients for this lane's 4 columns (one-sided baked in at edges)
    const float4 c1a = ld4(&g_cy1a[j0]);
    const float4 c1b = ld4(&g_cy1b[j0]);
    const float4 c1c = ld4(&g_cy1c[j0]);
    const float4 c2a = ld4(&g_cy2a[j0]);
    const float4 c2b = ld4(&g_cy2b[j0]);
    const float4 c2c = ld4(&g_cy2c[j0]);

    const bool e0b = (j0 == 0);            // column .x is the global left edge
    const bool e3b = (j0 + 3 == ny - 1);   // column .w is the global right edge
    const bool is_halo = (lane == 0) || (lane == 31);
    const int jh = (lane == 0) ? max(base - 1, 0) : min(base + 128, ny - 1);

    // Rolling window: rows i0-2, i0-1, i0, i0+1 (i-clamped)
    float4 u0, u1, u2, u3, v0, v1, v2, v3;
    {
        unsigned ra = (unsigned)max(i0 - 2, 0) * (unsigned)ny + (unsigned)j0;
        unsigned rb = (unsigned)max(i0 - 1, 0) * (unsigned)ny + (unsigned)j0;
        unsigned rc = (unsigned)i0 * (unsigned)ny + (unsigned)j0;
        unsigned rd = (unsigned)min(i0 + 1, nx - 1) * (unsigned)ny + (unsigned)j0;
        u0 = ld4(u + ra); u1 = ld4(u + rb); u2 = ld4(u + rc); u3 = ld4(u + rd);
        v0 = ld4(v + ra); v1 = ld4(v + rb); v2 = ld4(v + rc); v3 = ld4(v + rd);
    }

    unsigned o = (unsigned)i0 * (unsigned)ny + (unsigned)j0;

#pragma unroll
    for (int r = 0; r < RT; r++) {
        const int i = i0 + r;
        const float4 U = u2, V = v2;

        // Warp-edge neighbors via shuffle; lanes 0/31 patch from a direct load.
        float lu = __shfl_up_sync(FULLMASK, U.w, 1);
        float ru = __shfl_down_sync(FULLMASK, U.x, 1);
        float lv = __shfl_up_sync(FULLMASK, V.w, 1);
        float rv = __shfl_down_sync(FULLMASK, V.x, 1);
        float hu = 0.f, hv = 0.f;
        if (is_halo) {
            unsigned ho = (unsigned)i * (unsigned)ny + (unsigned)jh;
            hu = __ldg(u + ho);
            hv = __ldg(v + ho);
        }
        if (lane == 0)  { lu = hu; lv = hv; }
        if (lane == 31) { ru = hu; rv = hv; }

        // Per-element y-stencil triples. At j==0 the one-sided stencil reads
        // columns {0,1,2} = (.x,.y,.z); at j==ny-1 it reads (.y,.z,.w).
        float a0u = e0b ? U.x : lu,  b0u = e0b ? U.y : U.x, g0u = e0b ? U.z : U.y;
        float a0v = e0b ? V.x : lv,  b0v = e0b ? V.y : V.x, g0v = e0b ? V.z : V.y;
        float a3u = e3b ? U.y : U.z, b3u = e3b ? U.z : U.w, g3u = e3b ? U.w : ru;
        float a3v = e3b ? V.y : V.z, b3v = e3b ? V.z : V.w, g3v = e3b ? V.w : rv;

        float4 d1y_u, d2y_u, d1y_v, d2y_v;
        d1y_u.x = c1a.x * a0u + c1b.x * b0u + c1c.x * g0u;
        d2y_u.x = c2a.x * a0u + c2b.x * b0u + c2c.x * g0u;
        d1y_v.x = c1a.x * a0v + c1b.x * b0v + c1c.x * g0v;
        d2y_v.x = c2a.x * a0v + c2b.x * b0v + c2c.x * g0v;

        d1y_u.y = c1a.y * U.x + c1b.y * U.y + c1c.y * U.z;
        d2y_u.y = c2a.y * U.x + c2b.y * U.y + c2c.y * U.z;
        d1y_v.y = c1a.y * V.x + c1b.y * V.y + c1c.y * V.z;
        d2y_v.y = c2a.y * V.x + c2b.y * V.y + c2c.y * V.z;

        d1y_u.z = c1a.z * U.y + c1b.z * U.z + c1c.z * U.w;
        d2y_u.z = c2a.z * U.y + c2b.z * U.z + c2c.z * U.w;
        d1y_v.z = c1a.z * V.y + c1b.z * V.z + c1c.z * V.w;
        d2y_v.z = c2a.z * V.y + c2b.z * V.z + c2c.z * V.w;

        d1y_u.w = c1a.w * a3u + c1b.w * b3u + c1c.w * g3u;
        d2y_u.w = c2a.w * a3u + c2b.w * b3u + c2c.w * g3u;
        d1y_v.w = c1a.w * a3v + c1b.w * b3v + c1c.w * g3v;
        d2y_v.w = c2a.w * a3v + c2b.w * b3v + c2c.w * g3v;

        // x-stencil triple from the rolling window.
        // interior: rows i-1,i,i+1 = (u1,u2,u3); i==nx-1: rows nx-3..nx-1 = (u0,u1,u2)
        const bool last = (i == nx - 1);
        float4 X0 = last ? u0 : u1, X1 = last ? u1 : u2, X2 = last ? u2 : u3;
        float4 Y0 = last ? v0 : v1, Y1 = last ? v1 : v2, Y2 = last ? v2 : v3;

        const float4 cxa = g_cxA[i];   // warp-uniform
        const float2 cxb = g_cxB[i];

        float4 du, dv;
        {
            float d1x, d2x, d1xv, d2xv;
#define DO_ELEM(E) \
            d1x  = cxa.x * X0.E + cxa.y * X1.E + cxa.z * X2.E;            \
            d2x  = cxa.w * X0.E + cxb.x * X1.E + cxb.y * X2.E;            \
            d1xv = cxa.x * Y0.E + cxa.y * Y1.E + cxa.z * Y2.E;            \
            d2xv = cxa.w * Y0.E + cxb.x * Y1.E + cxb.y * Y2.E;            \
            du.E = mu * (d2y_u.E + d2x) - U.E * d1x - V.E * d1y_u.E + 0.01f; \
            dv.E = mu * (d2y_v.E + d2xv) - U.E * d1xv - V.E * d1y_v.E;
            DO_ELEM(x) DO_ELEM(y) DO_ELEM(z) DO_ELEM(w)
#undef DO_ELEM
        }

        // Boundary zeroing per reference (entire i==0 row zeroed for both)
        if (i == 0) { du = make_float4(0.f, 0.f, 0.f, 0.f);
                      dv = make_float4(0.f, 0.f, 0.f, 0.f); }
        if (e0b) { du.x = 0.f; dv.x = 0.f; }
        if (e3b) { du.w = 0.f; }

        st4(out + o, du);
        st4(out + plane + o, dv);
        o += (unsigned)ny;

        // Shift window and fetch the next row (skip after the final output row)
        if (r < RT - 1) {
            u0 = u1; u1 = u2; u2 = u3;
            v0 = v1; v1 = v2; v2 = v3;
            unsigned nr = (unsigned)min(i + 2, nx - 1) * (unsigned)ny + (unsigned)j0;
            u3 = ld4(u + nr);
            v3 = ld4(v + nr);
        }
    }
}

extern "C" void kernel_launch(void* const* d_in, const int* in_sizes, int n_in,
                              void* d_out, int out_size) {
    const float* state = (const float*)d_in[1];
    const float* x = (const float*)d_in[2];
    const float* y = (const float*)d_in[3];
    const float* mu = (const float*)d_in[4];
    int nx = in_sizes[2];
    int ny = in_sizes[3];
    float* out = (float*)d_out;

    int nmax = nx > ny ? nx : ny;
    coeff_kernel<<<(nmax + 255) / 256, 256>>>(x, nx, y, ny);

    dim3 block(32, 4);                        // warp = 128 columns, 16 i-rows/block
    dim3 grid((ny + 127) / 128, (nx + (4 * RT) - 1) / (4 * RT));
    rhs_kernel<<<grid, block>>>(state, mu, out, nx, ny);
}